// round 4
// baseline (speedup 1.0000x reference)
#include <cuda_runtime.h>

#define D    128
#define SEQ  4096
#define NQ   64
#define CH   16

// One CTA per (b, q). 256 threads.
//   Phase 1: scores s[n] = scale * dot(q, K[n])   (warp-per-row)
//   Phase 2: softmax over n (block reductions in smem)
//   Phase 3: acc[v][k] = sum_n (a[n]*V[n,v]) * K[n,k]   (8x8 register tiles)
//            o[v] = sum_n a[n]*V[n,v], w[k] = sum_n a[n]*K[n,k] as staging partials
//   Epilogue: J = scale * (acc - o[v]*w[k])
__global__ __launch_bounds__(256, 2)
void jac_kernel(const float* __restrict__ Q, const float* __restrict__ K,
                const float* __restrict__ V, float* __restrict__ out)
{
    __shared__ float q_sm[D];
    __shared__ float a_sm[SEQ];
    __shared__ float wv_sm[CH][D];     // a[n] * V rows (staged)
    __shared__ float kk_sm[CH][D];     // raw K rows (staged)
    __shared__ float opart_sm[8][D];   // o column-sum partials
    __shared__ float wpart_sm[8][D];   // w column-sum partials
    __shared__ float o_sm[D];
    __shared__ float w_sm[D];
    __shared__ float red_sm[8];

    const int tid  = threadIdx.x;
    const int lane = tid & 31;
    const int wid  = tid >> 5;
    const int q    = blockIdx.x;
    const int b    = blockIdx.y;

    const float* __restrict__ Kb = K + (size_t)b * SEQ * D;
    const float* __restrict__ Vb = V + (size_t)b * SEQ * D;
    const float* __restrict__ Qp = Q + ((size_t)b * NQ + q) * D;

    if (tid < 32) ((float4*)q_sm)[tid] = ((const float4*)Qp)[tid];
    __syncthreads();

    const float scale = 0.088388347648318447f;  // 1/sqrt(128)

    // ---------------- Phase 1: scores ----------------
    float4 qf = ((const float4*)q_sm)[lane];
    float lmax = -1e30f;
    for (int n = wid; n < SEQ; n += 8) {
        float4 kf = ((const float4*)(Kb + (size_t)n * D))[lane];
        float dp = qf.x*kf.x + qf.y*kf.y + qf.z*kf.z + qf.w*kf.w;
        dp += __shfl_xor_sync(0xffffffffu, dp, 16);
        dp += __shfl_xor_sync(0xffffffffu, dp, 8);
        dp += __shfl_xor_sync(0xffffffffu, dp, 4);
        dp += __shfl_xor_sync(0xffffffffu, dp, 2);
        dp += __shfl_xor_sync(0xffffffffu, dp, 1);
        dp *= scale;
        if (lane == 0) a_sm[n] = dp;
        lmax = fmaxf(lmax, dp);          // identical across lanes after reduce
    }
    if (lane == 0) red_sm[wid] = lmax;
    __syncthreads();
    float gmax = red_sm[0];
    #pragma unroll
    for (int i = 1; i < 8; i++) gmax = fmaxf(gmax, red_sm[i]);
    __syncthreads();   // everyone done reading red_sm before it's reused

    // ---------------- Phase 2: softmax ----------------
    float lsum = 0.f;
    for (int n = tid; n < SEQ; n += 256) {
        float e = __expf(a_sm[n] - gmax);
        a_sm[n] = e;
        lsum += e;
    }
    lsum += __shfl_xor_sync(0xffffffffu, lsum, 16);
    lsum += __shfl_xor_sync(0xffffffffu, lsum, 8);
    lsum += __shfl_xor_sync(0xffffffffu, lsum, 4);
    lsum += __shfl_xor_sync(0xffffffffu, lsum, 2);
    lsum += __shfl_xor_sync(0xffffffffu, lsum, 1);
    if (lane == 0) red_sm[wid] = lsum;
    __syncthreads();
    float gsum = 0.f;
    #pragma unroll
    for (int i = 0; i < 8; i++) gsum += red_sm[i];
    const float inv = 1.0f / gsum;
    for (int n = tid; n < SEQ; n += 256) a_sm[n] *= inv;
    // (first __syncthreads of the main loop fences these writes)

    // ---------------- Phase 3: main accumulation ----------------
    float acc[8][8];
    #pragma unroll
    for (int i = 0; i < 8; i++)
        #pragma unroll
        for (int j = 0; j < 8; j++) acc[i][j] = 0.f;

    float4 po = make_float4(0.f, 0.f, 0.f, 0.f);   // o partial (this thread's 4 cols)
    float4 pw = make_float4(0.f, 0.f, 0.f, 0.f);   // w partial

    const int r0 = tid >> 5;   // staging row 0..7 (and r0+8)
    const int c0 = tid & 31;   // staging float4 column
    const int tv = tid >> 4;   // output v-tile 0..15
    const int tk = tid & 15;   // output k-tile 0..15

    for (int n0 = 0; n0 < SEQ; n0 += CH) {
        __syncthreads();   // previous tile consumed (and a_sm normalized on iter 0)
        float a0 = a_sm[n0 + r0];
        float a1 = a_sm[n0 + r0 + 8];
        float4 v0 = ((const float4*)(Vb + (size_t)(n0 + r0    ) * D))[c0];
        float4 v1 = ((const float4*)(Vb + (size_t)(n0 + r0 + 8) * D))[c0];
        float4 k0 = ((const float4*)(Kb + (size_t)(n0 + r0    ) * D))[c0];
        float4 k1 = ((const float4*)(Kb + (size_t)(n0 + r0 + 8) * D))[c0];
        float4 w0 = make_float4(a0*v0.x, a0*v0.y, a0*v0.z, a0*v0.w);
        float4 w1 = make_float4(a1*v1.x, a1*v1.y, a1*v1.z, a1*v1.w);
        ((float4*)wv_sm[r0    ])[c0] = w0;
        ((float4*)wv_sm[r0 + 8])[c0] = w1;
        ((float4*)kk_sm[r0    ])[c0] = k0;
        ((float4*)kk_sm[r0 + 8])[c0] = k1;
        po.x += w0.x + w1.x;  po.y += w0.y + w1.y;
        po.z += w0.z + w1.z;  po.w += w0.w + w1.w;
        pw.x += a0*k0.x + a1*k1.x;  pw.y += a0*k0.y + a1*k1.y;
        pw.z += a0*k0.z + a1*k1.z;  pw.w += a0*k0.w + a1*k1.w;
        __syncthreads();

        #pragma unroll
        for (int r = 0; r < CH; r++) {
            float4 wa = *((const float4*)&wv_sm[r][tv*8]);
            float4 wb = *((const float4*)&wv_sm[r][tv*8 + 4]);
            float4 ka = *((const float4*)&kk_sm[r][tk*8]);
            float4 kb = *((const float4*)&kk_sm[r][tk*8 + 4]);
            float wv8[8] = {wa.x, wa.y, wa.z, wa.w, wb.x, wb.y, wb.z, wb.w};
            float kk8[8] = {ka.x, ka.y, ka.z, ka.w, kb.x, kb.y, kb.z, kb.w};
            #pragma unroll
            for (int i = 0; i < 8; i++)
                #pragma unroll
                for (int j = 0; j < 8; j++)
                    acc[i][j] += wv8[i] * kk8[j];
        }
    }

    // ---------------- reduce o / w partials ----------------
    ((float4*)opart_sm[r0])[c0] = po;
    ((float4*)wpart_sm[r0])[c0] = pw;
    __syncthreads();
    if (tid < D) {
        float s = 0.f;
        #pragma unroll
        for (int g = 0; g < 8; g++) s += opart_sm[g][tid];
        o_sm[tid] = s;
    } else {
        int t = tid - D;
        float s = 0.f;
        #pragma unroll
        for (int g = 0; g < 8; g++) s += wpart_sm[g][t];
        w_sm[t] = s;
    }
    __syncthreads();

    // ---------------- epilogue ----------------
    float ov[8], wk[8];
    #pragma unroll
    for (int i = 0; i < 8; i++) ov[i] = o_sm[tv*8 + i];
    #pragma unroll
    for (int j = 0; j < 8; j++) wk[j] = w_sm[tk*8 + j];

    float* outp = out + ((size_t)b * NQ + q) * D * D;
    #pragma unroll
    for (int i = 0; i < 8; i++) {
        int v = tv*8 + i;
        float vals[8];
        #pragma unroll
        for (int j = 0; j < 8; j++)
            vals[j] = scale * (acc[i][j] - ov[i] * wk[j]);
        float4 x0 = make_float4(vals[0], vals[1], vals[2], vals[3]);
        float4 x1 = make_float4(vals[4], vals[5], vals[6], vals[7]);
        float* rowp = outp + (size_t)v * D + tk*8;
        ((float4*)rowp)[0] = x0;
        ((float4*)rowp)[1] = x1;
    }
}

extern "C" void kernel_launch(void* const* d_in, const int* in_sizes, int n_in,
                              void* d_out, int out_size) {
    const float* Q = (const float*)d_in[0];
    const float* K = (const float*)d_in[1];
    const float* V = (const float*)d_in[2];
    float* out = (float*)d_out;
    int batch = in_sizes[0] / (NQ * D);
    dim3 grid(NQ, batch);
    jac_kernel<<<grid, 256>>>(Q, K, V, out);
}

// round 5
// speedup vs baseline: 1.0155x; 1.0155x over previous
#include <cuda_runtime.h>

#define D    128
#define SEQ  4096
#define NQ   64
#define CH   16

// One CTA per (b, q). 256 threads.
//   Phase 1: scores s[n] = scale * dot(q, K[n])   (warp-per-row)
//   Phase 2: softmax over n (block reductions in smem)
//   Phase 3: acc[v][k] = sum_n (a[n]*V[n,v]) * K[n,k]   (8x8 register tiles)
//            o[v] = sum_n a[n]*V[n,v], w[k] = sum_n a[n]*K[n,k] as staging partials
//   Epilogue: J = scale * (acc - o[v]*w[k])
__global__ __launch_bounds__(256, 2)
void jac_kernel(const float* __restrict__ Q, const float* __restrict__ K,
                const float* __restrict__ V, float* __restrict__ out)
{
    __shared__ float q_sm[D];
    __shared__ float a_sm[SEQ];
    __shared__ float wv_sm[CH][D];     // a[n] * V rows (staged)
    __shared__ float kk_sm[CH][D];     // raw K rows (staged)
    __shared__ float opart_sm[8][D];   // o column-sum partials
    __shared__ float wpart_sm[8][D];   // w column-sum partials
    __shared__ float o_sm[D];
    __shared__ float w_sm[D];
    __shared__ float red_sm[8];

    const int tid  = threadIdx.x;
    const int lane = tid & 31;
    const int wid  = tid >> 5;
    const int q    = blockIdx.x;
    const int b    = blockIdx.y;

    const float* __restrict__ Kb = K + (size_t)b * SEQ * D;
    const float* __restrict__ Vb = V + (size_t)b * SEQ * D;
    const float* __restrict__ Qp = Q + ((size_t)b * NQ + q) * D;

    if (tid < 32) ((float4*)q_sm)[tid] = ((const float4*)Qp)[tid];
    __syncthreads();

    const float scale = 0.088388347648318447f;  // 1/sqrt(128)

    // ---------------- Phase 1: scores ----------------
    float4 qf = ((const float4*)q_sm)[lane];
    float lmax = -1e30f;
    for (int n = wid; n < SEQ; n += 8) {
        float4 kf = ((const float4*)(Kb + (size_t)n * D))[lane];
        float dp = qf.x*kf.x + qf.y*kf.y + qf.z*kf.z + qf.w*kf.w;
        dp += __shfl_xor_sync(0xffffffffu, dp, 16);
        dp += __shfl_xor_sync(0xffffffffu, dp, 8);
        dp += __shfl_xor_sync(0xffffffffu, dp, 4);
        dp += __shfl_xor_sync(0xffffffffu, dp, 2);
        dp += __shfl_xor_sync(0xffffffffu, dp, 1);
        dp *= scale;
        if (lane == 0) a_sm[n] = dp;
        lmax = fmaxf(lmax, dp);          // identical across lanes after reduce
    }
    if (lane == 0) red_sm[wid] = lmax;
    __syncthreads();
    float gmax = red_sm[0];
    #pragma unroll
    for (int i = 1; i < 8; i++) gmax = fmaxf(gmax, red_sm[i]);
    __syncthreads();   // everyone done reading red_sm before it's reused

    // ---------------- Phase 2: softmax ----------------
    float lsum = 0.f;
    for (int n = tid; n < SEQ; n += 256) {
        float e = __expf(a_sm[n] - gmax);
        a_sm[n] = e;
        lsum += e;
    }
    lsum += __shfl_xor_sync(0xffffffffu, lsum, 16);
    lsum += __shfl_xor_sync(0xffffffffu, lsum, 8);
    lsum += __shfl_xor_sync(0xffffffffu, lsum, 4);
    lsum += __shfl_xor_sync(0xffffffffu, lsum, 2);
    lsum += __shfl_xor_sync(0xffffffffu, lsum, 1);
    if (lane == 0) red_sm[wid] = lsum;
    __syncthreads();
    float gsum = 0.f;
    #pragma unroll
    for (int i = 0; i < 8; i++) gsum += red_sm[i];
    const float inv = 1.0f / gsum;
    for (int n = tid; n < SEQ; n += 256) a_sm[n] *= inv;
    // (first __syncthreads of the main loop fences these writes)

    // ---------------- Phase 3: main accumulation ----------------
    float acc[8][8];
    #pragma unroll
    for (int i = 0; i < 8; i++)
        #pragma unroll
        for (int j = 0; j < 8; j++) acc[i][j] = 0.f;

    float4 po = make_float4(0.f, 0.f, 0.f, 0.f);   // o partial (this thread's 4 cols)
    float4 pw = make_float4(0.f, 0.f, 0.f, 0.f);   // w partial

    const int r0 = tid >> 5;   // staging row 0..7 (and r0+8)
    const int c0 = tid & 31;   // staging float4 column
    const int tv = tid >> 4;   // output v-tile 0..15
    const int tk = tid & 15;   // output k-tile 0..15

    for (int n0 = 0; n0 < SEQ; n0 += CH) {
        __syncthreads();   // previous tile consumed (and a_sm normalized on iter 0)
        float a0 = a_sm[n0 + r0];
        float a1 = a_sm[n0 + r0 + 8];
        float4 v0 = ((const float4*)(Vb + (size_t)(n0 + r0    ) * D))[c0];
        float4 v1 = ((const float4*)(Vb + (size_t)(n0 + r0 + 8) * D))[c0];
        float4 k0 = ((const float4*)(Kb + (size_t)(n0 + r0    ) * D))[c0];
        float4 k1 = ((const float4*)(Kb + (size_t)(n0 + r0 + 8) * D))[c0];
        float4 w0 = make_float4(a0*v0.x, a0*v0.y, a0*v0.z, a0*v0.w);
        float4 w1 = make_float4(a1*v1.x, a1*v1.y, a1*v1.z, a1*v1.w);
        ((float4*)wv_sm[r0    ])[c0] = w0;
        ((float4*)wv_sm[r0 + 8])[c0] = w1;
        ((float4*)kk_sm[r0    ])[c0] = k0;
        ((float4*)kk_sm[r0 + 8])[c0] = k1;
        po.x += w0.x + w1.x;  po.y += w0.y + w1.y;
        po.z += w0.z + w1.z;  po.w += w0.w + w1.w;
        pw.x += a0*k0.x + a1*k1.x;  pw.y += a0*k0.y + a1*k1.y;
        pw.z += a0*k0.z + a1*k1.z;  pw.w += a0*k0.w + a1*k1.w;
        __syncthreads();

        #pragma unroll
        for (int r = 0; r < CH; r++) {
            float4 wa = *((const float4*)&wv_sm[r][tv*8]);
            float4 wb = *((const float4*)&wv_sm[r][tv*8 + 4]);
            float4 ka = *((const float4*)&kk_sm[r][tk*8]);
            float4 kb = *((const float4*)&kk_sm[r][tk*8 + 4]);
            float wv8[8] = {wa.x, wa.y, wa.z, wa.w, wb.x, wb.y, wb.z, wb.w};
            float kk8[8] = {ka.x, ka.y, ka.z, ka.w, kb.x, kb.y, kb.z, kb.w};
            #pragma unroll
            for (int i = 0; i < 8; i++)
                #pragma unroll
                for (int j = 0; j < 8; j++)
                    acc[i][j] += wv8[i] * kk8[j];
        }
    }

    // ---------------- reduce o / w partials ----------------
    ((float4*)opart_sm[r0])[c0] = po;
    ((float4*)wpart_sm[r0])[c0] = pw;
    __syncthreads();
    if (tid < D) {
        float s = 0.f;
        #pragma unroll
        for (int g = 0; g < 8; g++) s += opart_sm[g][tid];
        o_sm[tid] = s;
    } else {
        int t = tid - D;
        float s = 0.f;
        #pragma unroll
        for (int g = 0; g < 8; g++) s += wpart_sm[g][t];
        w_sm[t] = s;
    }
    __syncthreads();

    // ---------------- epilogue ----------------
    float ov[8], wk[8];
    #pragma unroll
    for (int i = 0; i < 8; i++) ov[i] = o_sm[tv*8 + i];
    #pragma unroll
    for (int j = 0; j < 8; j++) wk[j] = w_sm[tk*8 + j];

    float* outp = out + ((size_t)b * NQ + q) * D * D;
    #pragma unroll
    for (int i = 0; i < 8; i++) {
        int v = tv*8 + i;
        float vals[8];
        #pragma unroll
        for (int j = 0; j < 8; j++)
            vals[j] = scale * (acc[i][j] - ov[i] * wk[j]);
        float4 x0 = make_float4(vals[0], vals[1], vals[2], vals[3]);
        float4 x1 = make_float4(vals[4], vals[5], vals[6], vals[7]);
        float* rowp = outp + (size_t)v * D + tk*8;
        ((float4*)rowp)[0] = x0;
        ((float4*)rowp)[1] = x1;
    }
}

extern "C" void kernel_launch(void* const* d_in, const int* in_sizes, int n_in,
                              void* d_out, int out_size) {
    const float* Q = (const float*)d_in[0];
    const float* K = (const float*)d_in[1];
    const float* V = (const float*)d_in[2];
    float* out = (float*)d_out;
    int batch = in_sizes[0] / (NQ * D);
    dim3 grid(NQ, batch);
    jac_kernel<<<grid, 256>>>(Q, K, V, out);
}

// round 6
// speedup vs baseline: 1.0469x; 1.0309x over previous
#include <cuda_runtime.h>
#include <cstdint>

#define D    128
#define SEQ  4096
#define NQ   64
#define CH   16

// Packed fp32x2 helpers (Blackwell FFMA2 — only reachable via PTX)
#define PACK2(out, lo, hi) \
    asm("mov.b64 %0, {%1, %2};" : "=l"(out) \
        : "r"(__float_as_uint(lo)), "r"(__float_as_uint(hi)))
#define UNPACK2(lo, hi, in) do { uint32_t _l, _h; \
    asm("mov.b64 {%0, %1}, %2;" : "=r"(_l), "=r"(_h) : "l"(in)); \
    lo = __uint_as_float(_l); hi = __uint_as_float(_h); } while (0)
__device__ __forceinline__ void ffma2(uint64_t& d, uint64_t a, uint64_t b) {
    asm("fma.rn.f32x2 %0, %1, %2, %0;" : "+l"(d) : "l"(a), "l"(b));
}

__global__ __launch_bounds__(256, 2)
void jac_kernel(const float* __restrict__ Q, const float* __restrict__ K,
                const float* __restrict__ V, float* __restrict__ out)
{
    __shared__ float q_sm[D];
    __shared__ float a_sm[SEQ];
    __shared__ float wv_sm[CH][D];
    __shared__ float kk_sm[CH][D];
    __shared__ float opart_sm[8][D];
    __shared__ float wpart_sm[8][D];
    __shared__ float o_sm[D];
    __shared__ float w_sm[D];
    __shared__ float red_sm[8];

    const int tid  = threadIdx.x;
    const int lane = tid & 31;
    const int wid  = tid >> 5;
    const int q    = blockIdx.x;
    const int b    = blockIdx.y;

    const float* __restrict__ Kb = K + (size_t)b * SEQ * D;
    const float* __restrict__ Vb = V + (size_t)b * SEQ * D;
    const float* __restrict__ Qp = Q + ((size_t)b * NQ + q) * D;

    if (tid < 32) ((float4*)q_sm)[tid] = ((const float4*)Qp)[tid];
    __syncthreads();

    const float scale = 0.088388347648318447f;  // 1/sqrt(128)

    // ---------------- Phase 1: scores ----------------
    float4 qf = ((const float4*)q_sm)[lane];
    float lmax = -1e30f;
    for (int n = wid; n < SEQ; n += 8) {
        float4 kf = ((const float4*)(Kb + (size_t)n * D))[lane];
        float dp = qf.x*kf.x + qf.y*kf.y + qf.z*kf.z + qf.w*kf.w;
        dp += __shfl_xor_sync(0xffffffffu, dp, 16);
        dp += __shfl_xor_sync(0xffffffffu, dp, 8);
        dp += __shfl_xor_sync(0xffffffffu, dp, 4);
        dp += __shfl_xor_sync(0xffffffffu, dp, 2);
        dp += __shfl_xor_sync(0xffffffffu, dp, 1);
        dp *= scale;
        if (lane == 0) a_sm[n] = dp;
        lmax = fmaxf(lmax, dp);
    }
    if (lane == 0) red_sm[wid] = lmax;
    __syncthreads();
    float gmax = red_sm[0];
    #pragma unroll
    for (int i = 1; i < 8; i++) gmax = fmaxf(gmax, red_sm[i]);
    __syncthreads();

    // ---------------- Phase 2: softmax ----------------
    float lsum = 0.f;
    for (int n = tid; n < SEQ; n += 256) {
        float e = __expf(a_sm[n] - gmax);
        a_sm[n] = e;
        lsum += e;
    }
    lsum += __shfl_xor_sync(0xffffffffu, lsum, 16);
    lsum += __shfl_xor_sync(0xffffffffu, lsum, 8);
    lsum += __shfl_xor_sync(0xffffffffu, lsum, 4);
    lsum += __shfl_xor_sync(0xffffffffu, lsum, 2);
    lsum += __shfl_xor_sync(0xffffffffu, lsum, 1);
    if (lane == 0) red_sm[wid] = lsum;
    __syncthreads();
    float gsum = 0.f;
    #pragma unroll
    for (int i = 0; i < 8; i++) gsum += red_sm[i];
    const float inv = 1.0f / gsum;
    for (int n = tid; n < SEQ; n += 256) a_sm[n] *= inv;

    // ---------------- Phase 3: packed-FMA accumulation ----------------
    uint64_t accp[8][4];
    const uint64_t z = 0;
    #pragma unroll
    for (int i = 0; i < 8; i++)
        #pragma unroll
        for (int j = 0; j < 4; j++) accp[i][j] = z;

    float4 po = make_float4(0.f, 0.f, 0.f, 0.f);
    float4 pw = make_float4(0.f, 0.f, 0.f, 0.f);

    const int r0 = tid >> 5;
    const int c0 = tid & 31;
    const int tv = tid >> 4;
    const int tk = tid & 15;

    for (int n0 = 0; n0 < SEQ; n0 += CH) {
        __syncthreads();
        float a0 = a_sm[n0 + r0];
        float a1 = a_sm[n0 + r0 + 8];
        float4 v0 = ((const float4*)(Vb + (size_t)(n0 + r0    ) * D))[c0];
        float4 v1 = ((const float4*)(Vb + (size_t)(n0 + r0 + 8) * D))[c0];
        float4 k0 = ((const float4*)(Kb + (size_t)(n0 + r0    ) * D))[c0];
        float4 k1 = ((const float4*)(Kb + (size_t)(n0 + r0 + 8) * D))[c0];
        float4 w0 = make_float4(a0*v0.x, a0*v0.y, a0*v0.z, a0*v0.w);
        float4 w1 = make_float4(a1*v1.x, a1*v1.y, a1*v1.z, a1*v1.w);
        ((float4*)wv_sm[r0    ])[c0] = w0;
        ((float4*)wv_sm[r0 + 8])[c0] = w1;
        ((float4*)kk_sm[r0    ])[c0] = k0;
        ((float4*)kk_sm[r0 + 8])[c0] = k1;
        po.x += w0.x + w1.x;  po.y += w0.y + w1.y;
        po.z += w0.z + w1.z;  po.w += w0.w + w1.w;
        pw.x += a0*k0.x + a1*k1.x;  pw.y += a0*k0.y + a1*k1.y;
        pw.z += a0*k0.z + a1*k1.z;  pw.w += a0*k0.w + a1*k1.w;
        __syncthreads();

        #pragma unroll
        for (int r = 0; r < CH; r++) {
            float4 wa = *((const float4*)&wv_sm[r][tv*8]);
            float4 wb = *((const float4*)&wv_sm[r][tv*8 + 4]);
            float4 ka = *((const float4*)&kk_sm[r][tk*8]);
            float4 kb = *((const float4*)&kk_sm[r][tk*8 + 4]);
            uint64_t kp[4], wp[8];
            PACK2(kp[0], ka.x, ka.y);  PACK2(kp[1], ka.z, ka.w);
            PACK2(kp[2], kb.x, kb.y);  PACK2(kp[3], kb.z, kb.w);
            PACK2(wp[0], wa.x, wa.x);  PACK2(wp[1], wa.y, wa.y);
            PACK2(wp[2], wa.z, wa.z);  PACK2(wp[3], wa.w, wa.w);
            PACK2(wp[4], wb.x, wb.x);  PACK2(wp[5], wb.y, wb.y);
            PACK2(wp[6], wb.z, wb.z);  PACK2(wp[7], wb.w, wb.w);
            #pragma unroll
            for (int i = 0; i < 8; i++)
                #pragma unroll
                for (int j = 0; j < 4; j++)
                    ffma2(accp[i][j], wp[i], kp[j]);
        }
    }

    // ---------------- reduce o / w partials ----------------
    ((float4*)opart_sm[r0])[c0] = po;
    ((float4*)wpart_sm[r0])[c0] = pw;
    __syncthreads();
    if (tid < D) {
        float s = 0.f;
        #pragma unroll
        for (int g = 0; g < 8; g++) s += opart_sm[g][tid];
        o_sm[tid] = s;
    } else {
        int t = tid - D;
        float s = 0.f;
        #pragma unroll
        for (int g = 0; g < 8; g++) s += wpart_sm[g][t];
        w_sm[t] = s;
    }
    __syncthreads();

    // ---------------- epilogue ----------------
    float ov[8], wk[8];
    #pragma unroll
    for (int i = 0; i < 8; i++) ov[i] = o_sm[tv*8 + i];
    #pragma unroll
    for (int j = 0; j < 8; j++) wk[j] = w_sm[tk*8 + j];

    float* outp = out + ((size_t)b * NQ + q) * D * D;
    #pragma unroll
    for (int i = 0; i < 8; i++) {
        int v = tv*8 + i;
        float vals[8];
        #pragma unroll
        for (int jp = 0; jp < 4; jp++) {
            float lo, hi;
            UNPACK2(lo, hi, accp[i][jp]);
            vals[2*jp]   = scale * (lo - ov[i] * wk[2*jp]);
            vals[2*jp+1] = scale * (hi - ov[i] * wk[2*jp+1]);
        }
        float4 x0 = make_float4(vals[0], vals[1], vals[2], vals[3]);
        float4 x1 = make_float4(vals[4], vals[5], vals[6], vals[7]);
        float* rowp = outp + (size_t)v * D + tk*8;
        ((float4*)rowp)[0] = x0;
        ((float4*)rowp)[1] = x1;
    }
}

extern "C" void kernel_launch(void* const* d_in, const int* in_sizes, int n_in,
                              void* d_out, int out_size) {
    const float* Q = (const float*)d_in[0];
    const float* K = (const float*)d_in[1];
    const float* V = (const float*)d_in[2];
    float* out = (float*)d_out;
    int batch = in_sizes[0] / (NQ * D);
    dim3 grid(NQ, batch);
    jac_kernel<<<grid, 256>>>(Q, K, V, out);
}

// round 8
// speedup vs baseline: 1.2992x; 1.2410x over previous
#include <cuda_runtime.h>
#include <cstdint>

#define SEQ  4096
#define NQ   64
#define DH   128
#define BMAX 16
#define SCALE 0.088388347648318447f
#define P 136                 // tile pitch in 32-bit words (conflict-free frags)
#define TILE_U (32*P)         // 4352 words per tile
#define DSMEM (4*TILE_U*4 + SEQ*4)   // 4 tiles + a_s = 86016 B

__device__ float g_Kr[(size_t)BMAX*SEQ*DH];   // tf32-rounded K
__device__ float g_Vr[(size_t)BMAX*SEQ*DH];   // tf32-rounded V

__device__ __forceinline__ float tf32r(float x) {
    uint32_t r;
    asm("cvt.rna.tf32.f32 %0, %1;" : "=r"(r) : "f"(x));
    return __uint_as_float(r);
}
__device__ __forceinline__ void mma_tf32(float* d, const uint32_t* a,
                                         uint32_t b0, uint32_t b1) {
    asm volatile(
        "mma.sync.aligned.m16n8k8.row.col.f32.tf32.tf32.f32 "
        "{%0,%1,%2,%3}, {%4,%5,%6,%7}, {%8,%9}, {%0,%1,%2,%3};"
        : "+f"(d[0]), "+f"(d[1]), "+f"(d[2]), "+f"(d[3])
        : "r"(a[0]), "r"(a[1]), "r"(a[2]), "r"(a[3]), "r"(b0), "r"(b1));
}

// ---- prep: round K,V to tf32 once ----
__global__ void prep_kernel(const float* __restrict__ K, const float* __restrict__ V,
                            int total4) {
    int i = blockIdx.x * blockDim.x + threadIdx.x;
    if (i >= total4) return;
    float4 k = ((const float4*)K)[i];
    float4 v = ((const float4*)V)[i];
    ((float4*)g_Kr)[i] = make_float4(tf32r(k.x), tf32r(k.y), tf32r(k.z), tf32r(k.w));
    ((float4*)g_Vr)[i] = make_float4(tf32r(v.x), tf32r(v.y), tf32r(v.z), tf32r(v.w));
}

// ---- main: one CTA per (b,q), tf32 mma.sync ----
__global__ __launch_bounds__(256, 1)
void jac_tc(const float* __restrict__ Q, const float* __restrict__ K,
            float* __restrict__ out)
{
    extern __shared__ uint32_t sm[];
    // [W0][W1][K0][K1][a_s]
    float* a_s = (float*)(sm + 4*TILE_U);
    __shared__ float q_sm[DH], o_sm[DH], w_sm[DH], red_sm[8];

    const int tid = threadIdx.x, lane = tid & 31, wid = tid >> 5;
    const int q = blockIdx.x, b = blockIdx.y;
    const float* __restrict__ Kb = K + (size_t)b * SEQ * DH;

    if (tid < 32) ((float4*)q_sm)[tid] =
        ((const float4*)(Q + ((size_t)b*NQ + q)*DH))[tid];
    __syncthreads();

    // ---- Phase 1: scores (exact fp32 Q.K) ----
    float4 qf = ((const float4*)q_sm)[lane];
    float lmax = -1e30f;
    for (int n = wid; n < SEQ; n += 8) {
        float4 kf = ((const float4*)(Kb + (size_t)n*DH))[lane];
        float dp = qf.x*kf.x + qf.y*kf.y + qf.z*kf.z + qf.w*kf.w;
        dp += __shfl_xor_sync(~0u, dp, 16); dp += __shfl_xor_sync(~0u, dp, 8);
        dp += __shfl_xor_sync(~0u, dp, 4);  dp += __shfl_xor_sync(~0u, dp, 2);
        dp += __shfl_xor_sync(~0u, dp, 1);
        dp *= SCALE;
        if (lane == 0) a_s[n] = dp;
        lmax = fmaxf(lmax, dp);
    }
    if (lane == 0) red_sm[wid] = lmax;
    __syncthreads();
    float gmax = red_sm[0];
    #pragma unroll
    for (int i = 1; i < 8; i++) gmax = fmaxf(gmax, red_sm[i]);
    __syncthreads();

    // ---- Phase 2: softmax ----
    float lsum = 0.f;
    for (int n = tid; n < SEQ; n += 256) {
        float e = __expf(a_s[n] - gmax); a_s[n] = e; lsum += e;
    }
    lsum += __shfl_xor_sync(~0u, lsum, 16); lsum += __shfl_xor_sync(~0u, lsum, 8);
    lsum += __shfl_xor_sync(~0u, lsum, 4);  lsum += __shfl_xor_sync(~0u, lsum, 2);
    lsum += __shfl_xor_sync(~0u, lsum, 1);
    if (lane == 0) red_sm[wid] = lsum;
    __syncthreads();
    float gsum = 0.f;
    #pragma unroll
    for (int i = 0; i < 8; i++) gsum += red_sm[i];
    const float inv = 1.0f / gsum;
    for (int n = tid; n < 256*16; n += 256) a_s[n] *= inv;
    __syncthreads();

    // ---- Phase 3: tf32 mma over 128 chunks of n=32 ----
    const float* Krb = g_Kr + (size_t)b*SEQ*DH;
    const float* Vrb = g_Vr + (size_t)b*SEQ*DH;
    const int sn = tid >> 3, sc = (tid & 7) * 16;       // staging: row, col base
    const int g = lane >> 2, ti = lane & 3;             // frag group / id
    const int v0 = (wid & 3) * 32, k0 = (wid >> 2) * 64;

    float pov[16], pwv[16];
    #pragma unroll
    for (int j = 0; j < 16; j++) { pov[j] = 0.f; pwv[j] = 0.f; }
    float acc[2][8][4];
    #pragma unroll
    for (int mi = 0; mi < 2; mi++)
        #pragma unroll
        for (int nj = 0; nj < 8; nj++)
            #pragma unroll
            for (int e = 0; e < 4; e++) acc[mi][nj][e] = 0.f;

    for (int ch = 0; ch < SEQ/32; ch++) {
        const int n0 = ch * 32, bsel = ch & 1;
        uint32_t* Wc = sm + bsel * TILE_U;
        uint32_t* Kc = sm + 2*TILE_U + bsel * TILE_U;
        {   // stage
            const int gn = n0 + sn;
            const float av = a_s[gn];
            const float4* vr = (const float4*)(Vrb + (size_t)gn*DH + sc);
            const float4* kr = (const float4*)(Krb + (size_t)gn*DH + sc);
            uint32_t* wd = Wc + sn*P + sc;
            uint32_t* kd = Kc + sn*P + sc;
            #pragma unroll
            for (int j = 0; j < 4; j++) {
                float4 kv = kr[j];
                pwv[4*j  ] += av*kv.x;  pwv[4*j+1] += av*kv.y;
                pwv[4*j+2] += av*kv.z;  pwv[4*j+3] += av*kv.w;
                *(uint4*)(kd + 4*j) = make_uint4(
                    __float_as_uint(kv.x), __float_as_uint(kv.y),
                    __float_as_uint(kv.z), __float_as_uint(kv.w));
                float4 vv = vr[j];
                float4 wv = make_float4(av*vv.x, av*vv.y, av*vv.z, av*vv.w);
                pov[4*j  ] += wv.x;  pov[4*j+1] += wv.y;
                pov[4*j+2] += wv.z;  pov[4*j+3] += wv.w;
                // +0x1000 = round-to-nearest into the tf32 bits HW reads
                *(uint4*)(wd + 4*j) = make_uint4(
                    __float_as_uint(wv.x)+0x1000u, __float_as_uint(wv.y)+0x1000u,
                    __float_as_uint(wv.z)+0x1000u, __float_as_uint(wv.w)+0x1000u);
            }
        }
        __syncthreads();
        #pragma unroll
        for (int s = 0; s < 4; s++) {
            const uint32_t* Wr0 = Wc + (s*8 + ti) * P;
            const uint32_t* Wr4 = Wr0 + 4*P;
            uint32_t af[2][4];
            #pragma unroll
            for (int mi = 0; mi < 2; mi++) {
                int cb = v0 + mi*16 + g;
                af[mi][0] = Wr0[cb];   af[mi][1] = Wr0[cb+8];
                af[mi][2] = Wr4[cb];   af[mi][3] = Wr4[cb+8];
            }
            const uint32_t* Kr0 = Kc + (s*8 + ti) * P;
            const uint32_t* Kr4 = Kr0 + 4*P;
            #pragma unroll
            for (int nj = 0; nj < 8; nj++) {
                int cb = k0 + nj*8 + g;
                uint32_t b0 = Kr0[cb], b1 = Kr4[cb];
                mma_tf32(acc[0][nj], af[0], b0, b1);
                mma_tf32(acc[1][nj], af[1], b0, b1);
            }
        }
    }
    __syncthreads();

    // ---- reduce o/w partials (reuse tile smem) ----
    float* opart = (float*)sm;               // [32][128]
    float* wpart = (float*)(sm + 2*TILE_U);  // [32][128]
    #pragma unroll
    for (int j = 0; j < 16; j++) {
        opart[sn*DH + sc + j] = pov[j];
        wpart[sn*DH + sc + j] = pwv[j];
    }
    __syncthreads();
    if (tid < DH) {
        float s = 0.f;
        #pragma unroll
        for (int n = 0; n < 32; n++) s += opart[n*DH + tid];
        o_sm[tid] = s;
    } else {
        int t = tid - DH;
        float s = 0.f;
        #pragma unroll
        for (int n = 0; n < 32; n++) s += wpart[n*DH + t];
        w_sm[t] = s;
    }
    __syncthreads();

    // ---- epilogue: J = SCALE * (acc - o v^T w) ----
    float* ob = out + ((size_t)b*NQ + q) * DH * DH;
    #pragma unroll
    for (int mi = 0; mi < 2; mi++) {
        int vr = v0 + mi*16 + g;
        float ov1 = o_sm[vr], ov2 = o_sm[vr + 8];
        #pragma unroll
        for (int nj = 0; nj < 8; nj++) {
            int kc = k0 + nj*8 + ti*2;
            float w1 = w_sm[kc], w2 = w_sm[kc+1];
            float2 r1 = make_float2(SCALE*(acc[mi][nj][0] - ov1*w1),
                                    SCALE*(acc[mi][nj][1] - ov1*w2));
            float2 r2 = make_float2(SCALE*(acc[mi][nj][2] - ov2*w1),
                                    SCALE*(acc[mi][nj][3] - ov2*w2));
            *(float2*)(ob + (size_t)vr*DH + kc)       = r1;
            *(float2*)(ob + (size_t)(vr+8)*DH + kc)   = r2;
        }
    }
}

extern "C" void kernel_launch(void* const* d_in, const int* in_sizes, int n_in,
                              void* d_out, int out_size) {
    const float* Q = (const float*)d_in[0];
    const float* K = (const float*)d_in[1];
    const float* V = (const float*)d_in[2];
    float* out = (float*)d_out;
    int batch = in_sizes[1] / (SEQ * DH);
    int total4 = batch * SEQ * DH / 4;
    prep_kernel<<<(total4 + 255)/256, 256>>>(K, V, total4);
    cudaFuncSetAttribute(jac_tc, cudaFuncAttributeMaxDynamicSharedMemorySize, DSMEM);
    jac_tc<<<dim3(NQ, batch), 256, DSMEM>>>(Q, K, out);
}

// round 10
// speedup vs baseline: 2.0921x; 1.6104x over previous
#include <cuda_runtime.h>
#include <cstdint>

#define SEQ  4096
#define NQ   64
#define DH   128
#define BMAX 16
#define SCALE 0.088388347648318447f
#define P 136
#define TILE_U (32*P)
#define NCH (SEQ/32)
#define DSMEM (4*TILE_U*4 + SEQ*4)

__device__ float g_Kr[(size_t)BMAX*SEQ*DH];
__device__ float g_Vr[(size_t)BMAX*SEQ*DH];

__device__ __forceinline__ float tf32r(float x) {
    uint32_t r;
    asm("cvt.rna.tf32.f32 %0, %1;" : "=r"(r) : "f"(x));
    return __uint_as_float(r);
}
__device__ __forceinline__ void mma_tf32(float* d, const uint32_t* a,
                                         uint32_t b0, uint32_t b1) {
    asm volatile(
        "mma.sync.aligned.m16n8k8.row.col.f32.tf32.tf32.f32 "
        "{%0,%1,%2,%3}, {%4,%5,%6,%7}, {%8,%9}, {%0,%1,%2,%3};"
        : "+f"(d[0]), "+f"(d[1]), "+f"(d[2]), "+f"(d[3])
        : "r"(a[0]), "r"(a[1]), "r"(a[2]), "r"(a[3]), "r"(b0), "r"(b1));
}

__global__ void prep_kernel(const float* __restrict__ K, const float* __restrict__ V,
                            int total4) {
    int i = blockIdx.x * blockDim.x + threadIdx.x;
    if (i >= total4) return;
    float4 k = ((const float4*)K)[i];
    float4 v = ((const float4*)V)[i];
    ((float4*)g_Kr)[i] = make_float4(tf32r(k.x), tf32r(k.y), tf32r(k.z), tf32r(k.w));
    ((float4*)g_Vr)[i] = make_float4(tf32r(v.x), tf32r(v.y), tf32r(v.z), tf32r(v.w));
}

struct F8 { float4 k0, k1, v0, v1; };

__device__ __forceinline__ void ld_chunk(F8& r, const float* Krb, const float* Vrb,
                                         int n0, int sn, int scb) {
    const float4* kp = (const float4*)(Krb + (size_t)(n0+sn)*DH + scb);
    const float4* vp = (const float4*)(Vrb + (size_t)(n0+sn)*DH + scb);
    r.k0 = kp[0]; r.k1 = kp[1]; r.v0 = vp[0]; r.v1 = vp[1];
}

__device__ __forceinline__ void stage(const F8& r, uint32_t* Kc, uint32_t* Wc,
                                      const float* a_s, int n0, int sn, int scb,
                                      float* pov, float* pwv) {
    float av = a_s[n0 + sn];
    uint32_t* kd = Kc + sn*P + scb;
    uint32_t* wd = Wc + sn*P + scb;
    pwv[0]+=av*r.k0.x; pwv[1]+=av*r.k0.y; pwv[2]+=av*r.k0.z; pwv[3]+=av*r.k0.w;
    pwv[4]+=av*r.k1.x; pwv[5]+=av*r.k1.y; pwv[6]+=av*r.k1.z; pwv[7]+=av*r.k1.w;
    *(uint4*)kd = make_uint4(__float_as_uint(r.k0.x), __float_as_uint(r.k0.y),
                             __float_as_uint(r.k0.z), __float_as_uint(r.k0.w));
    *(uint4*)(kd+4) = make_uint4(__float_as_uint(r.k1.x), __float_as_uint(r.k1.y),
                                 __float_as_uint(r.k1.z), __float_as_uint(r.k1.w));
    float4 w0 = make_float4(av*r.v0.x, av*r.v0.y, av*r.v0.z, av*r.v0.w);
    float4 w1 = make_float4(av*r.v1.x, av*r.v1.y, av*r.v1.z, av*r.v1.w);
    pov[0]+=w0.x; pov[1]+=w0.y; pov[2]+=w0.z; pov[3]+=w0.w;
    pov[4]+=w1.x; pov[5]+=w1.y; pov[6]+=w1.z; pov[7]+=w1.w;
    *(uint4*)wd = make_uint4(__float_as_uint(w0.x)+0x1000u, __float_as_uint(w0.y)+0x1000u,
                             __float_as_uint(w0.z)+0x1000u, __float_as_uint(w0.w)+0x1000u);
    *(uint4*)(wd+4) = make_uint4(__float_as_uint(w1.x)+0x1000u, __float_as_uint(w1.y)+0x1000u,
                                 __float_as_uint(w1.z)+0x1000u, __float_as_uint(w1.w)+0x1000u);
}

__device__ __forceinline__ void mma_phase(const uint32_t* Wc, const uint32_t* Kc,
                                          float (*acc)[4][4], int v0, int k0,
                                          int g, int ti) {
    #pragma unroll
    for (int s = 0; s < 4; s++) {
        const uint32_t* Wr0 = Wc + (s*8 + ti)*P;
        const uint32_t* Wr4 = Wr0 + 4*P;
        uint32_t af[2][4];
        #pragma unroll
        for (int mi = 0; mi < 2; mi++) {
            int cb = v0 + mi*16 + g;
            af[mi][0] = Wr0[cb];   af[mi][1] = Wr0[cb+8];
            af[mi][2] = Wr4[cb];   af[mi][3] = Wr4[cb+8];
        }
        const uint32_t* Kr0 = Kc + (s*8 + ti)*P;
        const uint32_t* Kr4 = Kr0 + 4*P;
        #pragma unroll
        for (int nj = 0; nj < 4; nj++) {
            int cb = k0 + nj*8 + g;
            uint32_t b0 = Kr0[cb], b1 = Kr4[cb];
            mma_tf32(acc[0][nj], af[0], b0, b1);
            mma_tf32(acc[1][nj], af[1], b0, b1);
        }
    }
}

__global__ __launch_bounds__(512, 1)
void jac_tc(const float* __restrict__ Q, const float* __restrict__ K,
            float* __restrict__ out)
{
    extern __shared__ uint32_t sm[];
    float* a_s = (float*)(sm + 4*TILE_U);
    __shared__ float q_sm[DH], o_sm[DH], w_sm[DH], red_sm[16];

    const int tid = threadIdx.x, lane = tid & 31, wid = tid >> 5;
    const int q = blockIdx.x, b = blockIdx.y;
    const float* __restrict__ Kb = K + (size_t)b * SEQ * DH;

    if (tid < 32) ((float4*)q_sm)[tid] =
        ((const float4*)(Q + ((size_t)b*NQ + q)*DH))[tid];
    __syncthreads();

    // ---- Phase 1: scores ----
    float4 qf = ((const float4*)q_sm)[lane];
    float lmax = -1e30f;
    for (int n = wid; n < SEQ; n += 16) {
        float4 kf = ((const float4*)(Kb + (size_t)n*DH))[lane];
        float dp = qf.x*kf.x + qf.y*kf.y + qf.z*kf.z + qf.w*kf.w;
        dp += __shfl_xor_sync(~0u, dp, 16); dp += __shfl_xor_sync(~0u, dp, 8);
        dp += __shfl_xor_sync(~0u, dp, 4);  dp += __shfl_xor_sync(~0u, dp, 2);
        dp += __shfl_xor_sync(~0u, dp, 1);
        dp *= SCALE;
        if (lane == 0) a_s[n] = dp;
        lmax = fmaxf(lmax, dp);
    }
    if (lane == 0) red_sm[wid] = lmax;
    __syncthreads();
    float gmax = red_sm[0];
    #pragma unroll
    for (int i = 1; i < 16; i++) gmax = fmaxf(gmax, red_sm[i]);
    __syncthreads();

    // ---- Phase 2: softmax ----
    float lsum = 0.f;
    for (int n = tid; n < SEQ; n += 512) {
        float e = __expf(a_s[n] - gmax); a_s[n] = e; lsum += e;
    }
    lsum += __shfl_xor_sync(~0u, lsum, 16); lsum += __shfl_xor_sync(~0u, lsum, 8);
    lsum += __shfl_xor_sync(~0u, lsum, 4);  lsum += __shfl_xor_sync(~0u, lsum, 2);
    lsum += __shfl_xor_sync(~0u, lsum, 1);
    if (lane == 0) red_sm[wid] = lsum;
    __syncthreads();
    float gsum = 0.f;
    #pragma unroll
    for (int i = 0; i < 16; i++) gsum += red_sm[i];
    const float inv = 1.0f / gsum;
    for (int n = tid; n < SEQ; n += 512) a_s[n] *= inv;
    __syncthreads();

    // ---- Phase 3: pipelined tf32 mma ----
    const float* Krb = g_Kr + (size_t)b*SEQ*DH;
    const float* Vrb = g_Vr + (size_t)b*SEQ*DH;
    const int sn = tid >> 4, scb = (tid & 15) * 8;
    const int g = lane >> 2, ti = lane & 3;
    const int v0 = (wid & 3) * 32, k0 = (wid >> 2) * 32;
    uint32_t* W0 = sm;             uint32_t* W1 = sm + TILE_U;
    uint32_t* K0 = sm + 2*TILE_U;  uint32_t* K1 = sm + 3*TILE_U;

    float pov[8], pwv[8];
    #pragma unroll
    for (int j = 0; j < 8; j++) { pov[j] = 0.f; pwv[j] = 0.f; }
    float acc[2][4][4];
    #pragma unroll
    for (int mi = 0; mi < 2; mi++)
        #pragma unroll
        for (int nj = 0; nj < 4; nj++)
            #pragma unroll
            for (int e = 0; e < 4; e++) acc[mi][nj][e] = 0.f;

    F8 ra, rb;
    ld_chunk(ra, Krb, Vrb, 0, sn, scb);
    for (int ch = 0; ch < NCH; ch += 2) {
        int n0 = ch * 32;
        stage(ra, K0, W0, a_s, n0, sn, scb, pov, pwv);
        ld_chunk(rb, Krb, Vrb, n0 + 32, sn, scb);
        __syncthreads();
        mma_phase(W0, K0, acc, v0, k0, g, ti);
        stage(rb, K1, W1, a_s, n0 + 32, sn, scb, pov, pwv);
        {
            int nn = (ch + 2 < NCH) ? (n0 + 64) : 0;   // clamp: dummy reload, unused
            ld_chunk(ra, Krb, Vrb, nn, sn, scb);
        }
        __syncthreads();
        mma_phase(W1, K1, acc, v0, k0, g, ti);
    }
    __syncthreads();

    // ---- reduce o/w partials (reuse tile smem) ----
    float* opart = (float*)sm;
    float* wpart = (float*)(sm + 2*TILE_U);
    #pragma unroll
    for (int j = 0; j < 8; j++) {
        opart[sn*DH + scb + j] = pov[j];
        wpart[sn*DH + scb + j] = pwv[j];
    }
    __syncthreads();
    if (tid < DH) {
        float s = 0.f;
        #pragma unroll
        for (int n = 0; n < 32; n++) s += opart[n*DH + tid];
        o_sm[tid] = s;
    } else if (tid < 2*DH) {
        int t = tid - DH;
        float s = 0.f;
        #pragma unroll
        for (int n = 0; n < 32; n++) s += wpart[n*DH + t];
        w_sm[t] = s;
    }
    __syncthreads();

    // ---- epilogue ----
    float* ob = out + ((size_t)b*NQ + q) * DH * DH;
    #pragma unroll
    for (int mi = 0; mi < 2; mi++) {
        int vr = v0 + mi*16 + g;
        float ov1 = o_sm[vr], ov2 = o_sm[vr + 8];
        #pragma unroll
        for (int nj = 0; nj < 4; nj++) {
            int kc = k0 + nj*8 + ti*2;
            float w1 = w_sm[kc], w2 = w_sm[kc+1];
            float2 r1 = make_float2(SCALE*(acc[mi][nj][0] - ov1*w1),
                                    SCALE*(acc[mi][nj][1] - ov1*w2));
            float2 r2 = make_float2(SCALE*(acc[mi][nj][2] - ov2*w1),
                                    SCALE*(acc[mi][nj][3] - ov2*w2));
            *(float2*)(ob + (size_t)vr*DH + kc)     = r1;
            *(float2*)(ob + (size_t)(vr+8)*DH + kc) = r2;
        }
    }
}

extern "C" void kernel_launch(void* const* d_in, const int* in_sizes, int n_in,
                              void* d_out, int out_size) {
    const float* Q = (const float*)d_in[0];
    const float* K = (const float*)d_in[1];
    const float* V = (const float*)d_in[2];
    float* out = (float*)d_out;
    int batch = in_sizes[1] / (SEQ * DH);
    int total4 = batch * SEQ * DH / 4;
    prep_kernel<<<(total4 + 255)/256, 256>>>(K, V, total4);
    cudaFuncSetAttribute(jac_tc, cudaFuncAttributeMaxDynamicSharedMemorySize, DSMEM);
    jac_tc<<<dim3(NQ, batch), 512, DSMEM>>>(Q, K, out);
}